// round 1
// baseline (speedup 1.0000x reference)
#include <cuda_runtime.h>
#include <math.h>

#define NA   50000
#define NEg  200000
#define NSg  1000000
#define AF   64
#define EWF  112
#define L2F  16
#define HIDF 128
#define OUTF 144

// Scratch (static device globals; no allocation allowed)
__device__ float g_PA[(size_t)NA * 256];        // per-atom: [f0|f1|s0|s1] each 64
__device__ float g_PE[(size_t)NEg * 128];       // per-edge: [f_e|s_e] each 64
__device__ float g_agg[(size_t)2 * NEg * 64];   // scatter target
__device__ float g_hid[(size_t)NEg * HIDF];     // stage-5 hidden

// ---------------------------------------------------------------------------
// Zero the scatter buffer (out buffer is poisoned; agg must start at 0)
// ---------------------------------------------------------------------------
__global__ void kZero() {
    size_t i = (size_t)blockIdx.x * blockDim.x + threadIdx.x;
    size_t n4 = (size_t)2 * NEg * 64 / 4;
    if (i < n4) reinterpret_cast<float4*>(g_agg)[i] = make_float4(0.f, 0.f, 0.f, 0.f);
}

// ---------------------------------------------------------------------------
// Kernel A: PA[a][m*64+c] = sum_k atom[a][k] * W(m)[k][c]
//   m=0: Wf rows 0..63  m=1: Wf rows 64..127  m=2: Ws rows 0..63  m=3: Ws 64..127
// block 256 threads (t = m*64+c), 32 atoms per block, weights in registers
// ---------------------------------------------------------------------------
__global__ __launch_bounds__(256) void kA(const float* __restrict__ atom,
                                          const float* __restrict__ Wf,
                                          const float* __restrict__ Ws) {
    int t = threadIdx.x;
    int m = t >> 6;
    int c = t & 63;
    const float* W = ((m < 2) ? Wf : Ws) + (size_t)(m & 1) * 64 * 64;
    float w[64];
#pragma unroll
    for (int k = 0; k < 64; k++) w[k] = W[k * 64 + c];

    __shared__ float xs[32][64];
    int a0 = blockIdx.x * 32;
    for (int i = t; i < 32 * 64; i += 256) {
        int a = a0 + (i >> 6);
        xs[i >> 6][i & 63] = (a < NA) ? atom[(size_t)a * 64 + (i & 63)] : 0.f;
    }
    __syncthreads();

    for (int j = 0; j < 32; j++) {
        int a = a0 + j;
        if (a >= NA) break;
        const float4* x4 = reinterpret_cast<const float4*>(xs[j]);
        float acc = 0.f;
#pragma unroll
        for (int k4 = 0; k4 < 16; k4++) {
            float4 v = x4[k4];
            acc = fmaf(v.x, w[4 * k4 + 0], acc);
            acc = fmaf(v.y, w[4 * k4 + 1], acc);
            acc = fmaf(v.z, w[4 * k4 + 2], acc);
            acc = fmaf(v.w, w[4 * k4 + 3], acc);
        }
        g_PA[(size_t)a * 256 + t] = acc;
    }
}

// ---------------------------------------------------------------------------
// Kernel B: PE[e][c] (c<64: Wf rows 128..239 ; c>=64: Ws rows 128..239)
// persistent blocks, W in smem, 32 edges/tile, 16-edge register tile
// ---------------------------------------------------------------------------
__global__ __launch_bounds__(256) void kB(const float* __restrict__ ef,
                                          const float* __restrict__ Wf,
                                          const float* __restrict__ Ws) {
    extern __shared__ float smB[];
    float* Wc = smB;                 // [112][128]
    float* xs = smB + 112 * 128;     // [32][112]
    int t = threadIdx.x;

    for (int i = t; i < 112 * 128; i += 256) {
        int k = i >> 7, c = i & 127;
        Wc[i] = (c < 64) ? Wf[(size_t)(128 + k) * 64 + c]
                         : Ws[(size_t)(128 + k) * 64 + (c - 64)];
    }
    __syncthreads();

    int c = t & 127, g = t >> 7;
    const int ntiles = NEg / 32;   // 6250
    for (int tile = blockIdx.x; tile < ntiles; tile += gridDim.x) {
        int e0 = tile * 32;
        __syncthreads();
        for (int i = t; i < 32 * 112; i += 256) {
            int el = i / 112, k = i - el * 112;
            xs[i] = ef[(size_t)(e0 + el) * 112 + k];
        }
        __syncthreads();

        float acc[16];
#pragma unroll
        for (int e = 0; e < 16; e++) acc[e] = 0.f;

#pragma unroll 4
        for (int k4 = 0; k4 < 28; k4++) {
            float w0 = Wc[(4 * k4 + 0) * 128 + c];
            float w1 = Wc[(4 * k4 + 1) * 128 + c];
            float w2 = Wc[(4 * k4 + 2) * 128 + c];
            float w3 = Wc[(4 * k4 + 3) * 128 + c];
#pragma unroll
            for (int e = 0; e < 16; e++) {
                float4 xv = reinterpret_cast<const float4*>(xs + (g * 16 + e) * 112)[k4];
                acc[e] = fmaf(xv.x, w0, acc[e]);
                acc[e] = fmaf(xv.y, w1, acc[e]);
                acc[e] = fmaf(xv.z, w2, acc[e]);
                acc[e] = fmaf(xv.w, w3, acc[e]);
            }
        }
#pragma unroll
        for (int e = 0; e < 16; e++)
            g_PE[(size_t)(e0 + g * 16 + e) * 128 + c] = acc[e];
    }
}

// ---------------------------------------------------------------------------
// Kernel C: per-sub gather + gate + decay + atomic scatter.
// One warp per sub row; lane l handles column pair (2l, 2l+1).
// ---------------------------------------------------------------------------
__device__ __forceinline__ float sigmf(float x) { return 1.f / (1.f + expf(-x)); }
__device__ __forceinline__ float softplusf(float x) {
    return fmaxf(x, 0.f) + log1pf(expf(-fabsf(x)));
}

__global__ __launch_bounds__(256) void kC(const int*   __restrict__ sai,
                                          const int*   __restrict__ sei,
                                          const float* __restrict__ ang,
                                          const int*   __restrict__ sidx,
                                          const float* __restrict__ dist,
                                          const float* __restrict__ Wf,
                                          const float* __restrict__ bf,
                                          const float* __restrict__ Ws,
                                          const float* __restrict__ bs) {
    int lane = threadIdx.x & 31;
    long wid  = ((long)blockIdx.x * blockDim.x + threadIdx.x) >> 5;
    long nwarps = ((long)gridDim.x * blockDim.x) >> 5;

    // per-lane constants: bias pair + 16 ang-weight pairs for each matrix
    float2 bfv = reinterpret_cast<const float2*>(bf)[lane];
    float2 bsv = reinterpret_cast<const float2*>(bs)[lane];
    float2 wfa[16], wsa[16];
#pragma unroll
    for (int k = 0; k < 16; k++) {
        wfa[k] = reinterpret_cast<const float2*>(Wf + (size_t)(240 + k) * 64)[lane];
        wsa[k] = reinterpret_cast<const float2*>(Ws + (size_t)(240 + k) * 64)[lane];
    }

    for (long s = wid; s < NSg; s += nwarps) {
        int i0 = sai[2 * s], i1 = sai[2 * s + 1];
        int e  = sei[s];
        int si = sidx[s];
        float d = dist[e];
        float decay = expf(-d * d * (1.0f / 18.0f));

        const float4* ap = reinterpret_cast<const float4*>(ang + (size_t)s * 16);
        float4 a0 = ap[0], a1 = ap[1], a2 = ap[2], a3 = ap[3];
        float av[16] = {a0.x,a0.y,a0.z,a0.w, a1.x,a1.y,a1.z,a1.w,
                        a2.x,a2.y,a2.z,a2.w, a3.x,a3.y,a3.z,a3.w};

        const float2* pa0 = reinterpret_cast<const float2*>(g_PA + (size_t)i0 * 256);
        const float2* pa1 = reinterpret_cast<const float2*>(g_PA + (size_t)i1 * 256);
        const float2* pe  = reinterpret_cast<const float2*>(g_PE + (size_t)e  * 128);

        float2 f1 = pa0[lane];        // m0 slice of atom i0
        float2 f2 = pa1[32 + lane];   // m1 slice of atom i1
        float2 f3 = pe[lane];         // edge f slice
        float2 s1 = pa0[64 + lane];   // m2
        float2 s2 = pa1[96 + lane];   // m3
        float2 s3 = pe[32 + lane];    // edge s slice

        float vfx = f1.x + f2.x + f3.x + bfv.x;
        float vfy = f1.y + f2.y + f3.y + bfv.y;
        float vsx = s1.x + s2.x + s3.x + bsv.x;
        float vsy = s1.y + s2.y + s3.y + bsv.y;

#pragma unroll
        for (int k = 0; k < 16; k++) {
            vfx = fmaf(av[k], wfa[k].x, vfx);
            vfy = fmaf(av[k], wfa[k].y, vfy);
            vsx = fmaf(av[k], wsa[k].x, vsx);
            vsy = fmaf(av[k], wsa[k].y, vsy);
        }

        float ox = sigmf(vfx) * softplusf(vsx) * decay;
        float oy = sigmf(vfy) * softplusf(vsy) * decay;

        float* dst = g_agg + (size_t)si * 64 + 2 * lane;
        atomicAdd(dst,     ox);
        atomicAdd(dst + 1, oy);
    }
}

// ---------------------------------------------------------------------------
// Kernel D1: hid = silu([agg0|agg1|ef] @ W1 + b1), W1 resident in smem
// persistent, 32 edges/tile, 256 threads (c = t&127, g = t>>7, 16 edges each)
// ---------------------------------------------------------------------------
__global__ __launch_bounds__(256) void kD1(const float* __restrict__ ef,
                                           const float* __restrict__ W1,
                                           const float* __restrict__ b1) {
    extern __shared__ float smD1[];
    float* W1s = smD1;                 // [240][128]
    float* xs  = smD1 + 240 * 128;     // [32][240]
    int t = threadIdx.x;

    for (int i = t; i < 240 * 128; i += 256) W1s[i] = W1[i];
    __syncthreads();

    int c = t & 127, g = t >> 7;
    float bias = b1[c];
    const int ntiles = NEg / 32;
    for (int tile = blockIdx.x; tile < ntiles; tile += gridDim.x) {
        int e0 = tile * 32;
        __syncthreads();
        for (int i = t; i < 32 * 240; i += 256) {
            int el = i / 240, k = i - el * 240;
            int e = e0 + el;
            xs[i] = (k < 128) ? g_agg[(size_t)e * 128 + k]
                              : ef[(size_t)e * 112 + (k - 128)];
        }
        __syncthreads();

        float acc[16];
#pragma unroll
        for (int e = 0; e < 16; e++) acc[e] = 0.f;

#pragma unroll 4
        for (int k4 = 0; k4 < 60; k4++) {
            float w0 = W1s[(4 * k4 + 0) * 128 + c];
            float w1 = W1s[(4 * k4 + 1) * 128 + c];
            float w2 = W1s[(4 * k4 + 2) * 128 + c];
            float w3 = W1s[(4 * k4 + 3) * 128 + c];
#pragma unroll
            for (int e = 0; e < 16; e++) {
                float4 xv = reinterpret_cast<const float4*>(xs + (g * 16 + e) * 240)[k4];
                acc[e] = fmaf(xv.x, w0, acc[e]);
                acc[e] = fmaf(xv.y, w1, acc[e]);
                acc[e] = fmaf(xv.z, w2, acc[e]);
                acc[e] = fmaf(xv.w, w3, acc[e]);
            }
        }
#pragma unroll
        for (int e = 0; e < 16; e++) {
            float v = acc[e] + bias;
            float h = v / (1.f + expf(-v));   // silu
            g_hid[(size_t)(e0 + g * 16 + e) * 128 + c] = h;
        }
    }
}

// ---------------------------------------------------------------------------
// Kernel D2: out = hid @ W2 + b2, W2 resident in smem
// block 288 threads (c = t%144, g = t/144, 16 edges each)
// ---------------------------------------------------------------------------
__global__ __launch_bounds__(288) void kD2(const float* __restrict__ W2,
                                           const float* __restrict__ b2,
                                           float* __restrict__ out) {
    extern __shared__ float smD2[];
    float* W2s = smD2;                 // [128][144]
    float* xs  = smD2 + 128 * 144;     // [32][128]
    int t = threadIdx.x;

    for (int i = t; i < 128 * 144; i += 288) W2s[i] = W2[i];
    __syncthreads();

    int c = t % 144, g = t / 144;
    float bias = b2[c];
    const int ntiles = NEg / 32;
    for (int tile = blockIdx.x; tile < ntiles; tile += gridDim.x) {
        int e0 = tile * 32;
        __syncthreads();
        for (int i = t; i < 32 * 128; i += 288)
            xs[i] = g_hid[(size_t)e0 * 128 + i];
        __syncthreads();

        float acc[16];
#pragma unroll
        for (int e = 0; e < 16; e++) acc[e] = 0.f;

#pragma unroll 4
        for (int k4 = 0; k4 < 32; k4++) {
            float w0 = W2s[(4 * k4 + 0) * 144 + c];
            float w1 = W2s[(4 * k4 + 1) * 144 + c];
            float w2 = W2s[(4 * k4 + 2) * 144 + c];
            float w3 = W2s[(4 * k4 + 3) * 144 + c];
#pragma unroll
            for (int e = 0; e < 16; e++) {
                float4 xv = reinterpret_cast<const float4*>(xs + (g * 16 + e) * 128)[k4];
                acc[e] = fmaf(xv.x, w0, acc[e]);
                acc[e] = fmaf(xv.y, w1, acc[e]);
                acc[e] = fmaf(xv.z, w2, acc[e]);
                acc[e] = fmaf(xv.w, w3, acc[e]);
            }
        }
#pragma unroll
        for (int e = 0; e < 16; e++)
            out[(size_t)(e0 + g * 16 + e) * 144 + c] = acc[e] + bias;
    }
}

// ---------------------------------------------------------------------------
extern "C" void kernel_launch(void* const* d_in, const int* in_sizes, int n_in,
                              void* d_out, int out_size) {
    const float* atom_fea = (const float*)d_in[0];
    const float* edge_fea = (const float*)d_in[1];
    const int*   sai      = (const int*)  d_in[2];
    const int*   sei      = (const int*)  d_in[3];
    const float* ang      = (const float*)d_in[4];
    const int*   sidx     = (const int*)  d_in[5];
    const float* dist     = (const float*)d_in[6];
    const float* Wf       = (const float*)d_in[7];
    const float* bf       = (const float*)d_in[8];
    const float* Ws       = (const float*)d_in[9];
    const float* bs       = (const float*)d_in[10];
    const float* W1       = (const float*)d_in[11];
    const float* b1       = (const float*)d_in[12];
    const float* W2       = (const float*)d_in[13];
    const float* b2       = (const float*)d_in[14];
    float* out = (float*)d_out;

    static bool attr_done = false;
    if (!attr_done) {
        cudaFuncSetAttribute(kB,  cudaFuncAttributeMaxDynamicSharedMemorySize, 112*128*4 + 32*112*4);
        cudaFuncSetAttribute(kD1, cudaFuncAttributeMaxDynamicSharedMemorySize, 240*128*4 + 32*240*4);
        cudaFuncSetAttribute(kD2, cudaFuncAttributeMaxDynamicSharedMemorySize, 128*144*4 + 32*128*4);
        attr_done = true;
    }

    // zero scatter buffer
    {
        size_t n4 = (size_t)2 * NEg * 64 / 4;
        int blocks = (int)((n4 + 255) / 256);
        kZero<<<blocks, 256>>>();
    }
    // per-atom projections
    kA<<<(NA + 31) / 32, 256>>>(atom_fea, Wf, Ws);
    // per-edge projections
    kB<<<444, 256, 112*128*4 + 32*112*4>>>(edge_fea, Wf, Ws);
    // per-sub gather/gate/scatter
    kC<<<2048, 256>>>(sai, sei, ang, sidx, dist, Wf, bf, Ws, bs);
    // edge MLP
    kD1<<<148, 256, 240*128*4 + 32*240*4>>>(edge_fea, W1, b1);
    kD2<<<296, 288, 128*144*4 + 32*128*4>>>(W2, b2, out);
}

// round 2
// speedup vs baseline: 1.1740x; 1.1740x over previous
#include <cuda_runtime.h>
#include <math.h>

#define NA   50000
#define NEg  200000
#define NSg  1000000
#define AF   64
#define EWF  112
#define L2F  16
#define HIDF 128
#define OUTF 144

// Scratch (static device globals; no allocation allowed)
__device__ float g_PA[(size_t)NA * 256];        // per-atom: [f0|f1|s0|s1] each 64
__device__ float g_PE[(size_t)NEg * 128];       // per-edge: [f_e|s_e] each 64
__device__ float g_agg[(size_t)2 * NEg * 64];   // scatter target
__device__ float g_hid[(size_t)NEg * HIDF];     // stage-5 hidden

// ---------------------------------------------------------------------------
// Zero the scatter buffer (out buffer is poisoned; agg must start at 0)
// ---------------------------------------------------------------------------
__global__ void kZero() {
    size_t i = (size_t)blockIdx.x * blockDim.x + threadIdx.x;
    size_t n4 = (size_t)2 * NEg * 64 / 4;
    if (i < n4) reinterpret_cast<float4*>(g_agg)[i] = make_float4(0.f, 0.f, 0.f, 0.f);
}

// ---------------------------------------------------------------------------
// Kernel A: PA[a][m*64+c] = sum_k atom[a][k] * W(m)[k][c]
//   m=0: Wf rows 0..63  m=1: Wf rows 64..127  m=2: Ws rows 0..63  m=3: Ws 64..127
// ---------------------------------------------------------------------------
__global__ __launch_bounds__(256) void kA(const float* __restrict__ atom,
                                          const float* __restrict__ Wf,
                                          const float* __restrict__ Ws) {
    int t = threadIdx.x;
    int m = t >> 6;
    int c = t & 63;
    const float* W = ((m < 2) ? Wf : Ws) + (size_t)(m & 1) * 64 * 64;
    float w[64];
#pragma unroll
    for (int k = 0; k < 64; k++) w[k] = W[k * 64 + c];

    __shared__ float xs[32][64];
    int a0 = blockIdx.x * 32;
    for (int i = t; i < 32 * 64; i += 256) {
        int a = a0 + (i >> 6);
        xs[i >> 6][i & 63] = (a < NA) ? atom[(size_t)a * 64 + (i & 63)] : 0.f;
    }
    __syncthreads();

    for (int j = 0; j < 32; j++) {
        int a = a0 + j;
        if (a >= NA) break;
        const float4* x4 = reinterpret_cast<const float4*>(xs[j]);
        float acc = 0.f;
#pragma unroll
        for (int k4 = 0; k4 < 16; k4++) {
            float4 v = x4[k4];
            acc = fmaf(v.x, w[4 * k4 + 0], acc);
            acc = fmaf(v.y, w[4 * k4 + 1], acc);
            acc = fmaf(v.z, w[4 * k4 + 2], acc);
            acc = fmaf(v.w, w[4 * k4 + 3], acc);
        }
        g_PA[(size_t)a * 256 + t] = acc;
    }
}

// ---------------------------------------------------------------------------
// Kernel B: PE[e][c] (c<64: Wf rows 128..239 ; c>=64: Ws rows 128..239)
// ---------------------------------------------------------------------------
__global__ __launch_bounds__(256) void kB(const float* __restrict__ ef,
                                          const float* __restrict__ Wf,
                                          const float* __restrict__ Ws) {
    extern __shared__ float smB[];
    float* Wc = smB;                 // [112][128]
    float* xs = smB + 112 * 128;     // [32][112]
    int t = threadIdx.x;

    for (int i = t; i < 112 * 128; i += 256) {
        int k = i >> 7, c = i & 127;
        Wc[i] = (c < 64) ? Wf[(size_t)(128 + k) * 64 + c]
                         : Ws[(size_t)(128 + k) * 64 + (c - 64)];
    }
    __syncthreads();

    int c = t & 127, g = t >> 7;
    const int ntiles = NEg / 32;   // 6250
    for (int tile = blockIdx.x; tile < ntiles; tile += gridDim.x) {
        int e0 = tile * 32;
        __syncthreads();
        for (int i = t; i < 32 * 112; i += 256) {
            int el = i / 112, k = i - el * 112;
            xs[i] = ef[(size_t)(e0 + el) * 112 + k];
        }
        __syncthreads();

        float acc[16];
#pragma unroll
        for (int e = 0; e < 16; e++) acc[e] = 0.f;

#pragma unroll 4
        for (int k4 = 0; k4 < 28; k4++) {
            float w0 = Wc[(4 * k4 + 0) * 128 + c];
            float w1 = Wc[(4 * k4 + 1) * 128 + c];
            float w2 = Wc[(4 * k4 + 2) * 128 + c];
            float w3 = Wc[(4 * k4 + 3) * 128 + c];
#pragma unroll
            for (int e = 0; e < 16; e++) {
                float4 xv = reinterpret_cast<const float4*>(xs + (g * 16 + e) * 112)[k4];
                acc[e] = fmaf(xv.x, w0, acc[e]);
                acc[e] = fmaf(xv.y, w1, acc[e]);
                acc[e] = fmaf(xv.z, w2, acc[e]);
                acc[e] = fmaf(xv.w, w3, acc[e]);
            }
        }
#pragma unroll
        for (int e = 0; e < 16; e++)
            g_PE[(size_t)(e0 + g * 16 + e) * 128 + c] = acc[e];
    }
}

// ---------------------------------------------------------------------------
// Kernel C: per-sub gather + gate + decay + atomic scatter.
// One warp per sub row; lane l handles column pair (2l, 2l+1).
// v2: ang-weights in SMEM (regs 104 -> ~56), fast-math transcendentals.
// ---------------------------------------------------------------------------
__global__ __launch_bounds__(256) void kC(const int*   __restrict__ sai,
                                          const int*   __restrict__ sei,
                                          const float* __restrict__ ang,
                                          const int*   __restrict__ sidx,
                                          const float* __restrict__ dist,
                                          const float* __restrict__ Wf,
                                          const float* __restrict__ bf,
                                          const float* __restrict__ Ws,
                                          const float* __restrict__ bs) {
    __shared__ float2 swf[16][32];
    __shared__ float2 sws[16][32];
    int t = threadIdx.x;
    for (int i = t; i < 512; i += 256) {
        int k = i >> 5, l = i & 31;
        swf[k][l] = reinterpret_cast<const float2*>(Wf + (size_t)(240 + k) * 64)[l];
        sws[k][l] = reinterpret_cast<const float2*>(Ws + (size_t)(240 + k) * 64)[l];
    }
    __syncthreads();

    int lane = t & 31;
    float2 bfv = reinterpret_cast<const float2*>(bf)[lane];
    float2 bsv = reinterpret_cast<const float2*>(bs)[lane];

    unsigned wid = ((unsigned)blockIdx.x * blockDim.x + t) >> 5;
    unsigned nwarps = ((unsigned)gridDim.x * blockDim.x) >> 5;

    for (unsigned s = wid; s < NSg; s += nwarps) {
        int i0 = sai[2 * s], i1 = sai[2 * s + 1];
        int e  = sei[s];
        int si = sidx[s];
        float d = dist[e];
        float decay = __expf(-d * d * (1.0f / 18.0f));

        const float4* ap = reinterpret_cast<const float4*>(ang + (size_t)s * 16);
        float4 a0 = ap[0], a1 = ap[1], a2 = ap[2], a3 = ap[3];
        float av[16] = {a0.x,a0.y,a0.z,a0.w, a1.x,a1.y,a1.z,a1.w,
                        a2.x,a2.y,a2.z,a2.w, a3.x,a3.y,a3.z,a3.w};

        const float2* pa0 = reinterpret_cast<const float2*>(g_PA + (size_t)i0 * 256);
        const float2* pa1 = reinterpret_cast<const float2*>(g_PA + (size_t)i1 * 256);
        const float2* pe  = reinterpret_cast<const float2*>(g_PE + (size_t)e  * 128);

        float2 f1 = pa0[lane];        // m0 slice of atom i0
        float2 f2 = pa1[32 + lane];   // m1 slice of atom i1
        float2 f3 = pe[lane];         // edge f slice
        float2 s1 = pa0[64 + lane];   // m2
        float2 s2 = pa1[96 + lane];   // m3
        float2 s3 = pe[32 + lane];    // edge s slice

        float vfx = f1.x + f2.x + f3.x + bfv.x;
        float vfy = f1.y + f2.y + f3.y + bfv.y;
        float vsx = s1.x + s2.x + s3.x + bsv.x;
        float vsy = s1.y + s2.y + s3.y + bsv.y;

#pragma unroll 4
        for (int k = 0; k < 16; k++) {
            float2 wf2 = swf[k][lane];
            float2 ws2 = sws[k][lane];
            float a = av[k];
            vfx = fmaf(a, wf2.x, vfx);
            vfy = fmaf(a, wf2.y, vfy);
            vsx = fmaf(a, ws2.x, vsx);
            vsy = fmaf(a, ws2.y, vsy);
        }

        // sigmoid(vf) * softplus(vs) * decay, fast-math
        float sgx = __fdividef(1.f, 1.f + __expf(-vfx));
        float sgy = __fdividef(1.f, 1.f + __expf(-vfy));
        float spx = fmaxf(vsx, 0.f) + __logf(1.f + __expf(-fabsf(vsx)));
        float spy = fmaxf(vsy, 0.f) + __logf(1.f + __expf(-fabsf(vsy)));

        float ox = sgx * spx * decay;
        float oy = sgy * spy * decay;

        float* dst = g_agg + (size_t)si * 64 + 2 * lane;
        atomicAdd(dst,     ox);
        atomicAdd(dst + 1, oy);
    }
}

// ---------------------------------------------------------------------------
// Kernel D1: hid = silu([agg0|agg1|ef] @ W1 + b1), W1 resident in smem
// ---------------------------------------------------------------------------
__global__ __launch_bounds__(256) void kD1(const float* __restrict__ ef,
                                           const float* __restrict__ W1,
                                           const float* __restrict__ b1) {
    extern __shared__ float smD1[];
    float* W1s = smD1;                 // [240][128]
    float* xs  = smD1 + 240 * 128;     // [32][240]
    int t = threadIdx.x;

    for (int i = t; i < 240 * 128; i += 256) W1s[i] = W1[i];
    __syncthreads();

    int c = t & 127, g = t >> 7;
    float bias = b1[c];
    const int ntiles = NEg / 32;
    for (int tile = blockIdx.x; tile < ntiles; tile += gridDim.x) {
        int e0 = tile * 32;
        __syncthreads();
        for (int i = t; i < 32 * 240; i += 256) {
            int el = i / 240, k = i - el * 240;
            int e = e0 + el;
            xs[i] = (k < 128) ? g_agg[(size_t)e * 128 + k]
                              : ef[(size_t)e * 112 + (k - 128)];
        }
        __syncthreads();

        float acc[16];
#pragma unroll
        for (int e = 0; e < 16; e++) acc[e] = 0.f;

#pragma unroll 4
        for (int k4 = 0; k4 < 60; k4++) {
            float w0 = W1s[(4 * k4 + 0) * 128 + c];
            float w1 = W1s[(4 * k4 + 1) * 128 + c];
            float w2 = W1s[(4 * k4 + 2) * 128 + c];
            float w3 = W1s[(4 * k4 + 3) * 128 + c];
#pragma unroll
            for (int e = 0; e < 16; e++) {
                float4 xv = reinterpret_cast<const float4*>(xs + (g * 16 + e) * 240)[k4];
                acc[e] = fmaf(xv.x, w0, acc[e]);
                acc[e] = fmaf(xv.y, w1, acc[e]);
                acc[e] = fmaf(xv.z, w2, acc[e]);
                acc[e] = fmaf(xv.w, w3, acc[e]);
            }
        }
#pragma unroll
        for (int e = 0; e < 16; e++) {
            float v = acc[e] + bias;
            float h = v * __fdividef(1.f, 1.f + __expf(-v));   // silu
            g_hid[(size_t)(e0 + g * 16 + e) * 128 + c] = h;
        }
    }
}

// ---------------------------------------------------------------------------
// Kernel D2: out = hid @ W2 + b2, W2 resident in smem
// ---------------------------------------------------------------------------
__global__ __launch_bounds__(288) void kD2(const float* __restrict__ W2,
                                           const float* __restrict__ b2,
                                           float* __restrict__ out) {
    extern __shared__ float smD2[];
    float* W2s = smD2;                 // [128][144]
    float* xs  = smD2 + 128 * 144;     // [32][128]
    int t = threadIdx.x;

    for (int i = t; i < 128 * 144; i += 288) W2s[i] = W2[i];
    __syncthreads();

    int c = t % 144, g = t / 144;
    float bias = b2[c];
    const int ntiles = NEg / 32;
    for (int tile = blockIdx.x; tile < ntiles; tile += gridDim.x) {
        int e0 = tile * 32;
        __syncthreads();
        for (int i = t; i < 32 * 128; i += 288)
            xs[i] = g_hid[(size_t)e0 * 128 + i];
        __syncthreads();

        float acc[16];
#pragma unroll
        for (int e = 0; e < 16; e++) acc[e] = 0.f;

#pragma unroll 4
        for (int k4 = 0; k4 < 32; k4++) {
            float w0 = W2s[(4 * k4 + 0) * 144 + c];
            float w1 = W2s[(4 * k4 + 1) * 144 + c];
            float w2 = W2s[(4 * k4 + 2) * 144 + c];
            float w3 = W2s[(4 * k4 + 3) * 144 + c];
#pragma unroll
            for (int e = 0; e < 16; e++) {
                float4 xv = reinterpret_cast<const float4*>(xs + (g * 16 + e) * 128)[k4];
                acc[e] = fmaf(xv.x, w0, acc[e]);
                acc[e] = fmaf(xv.y, w1, acc[e]);
                acc[e] = fmaf(xv.z, w2, acc[e]);
                acc[e] = fmaf(xv.w, w3, acc[e]);
            }
        }
#pragma unroll
        for (int e = 0; e < 16; e++)
            out[(size_t)(e0 + g * 16 + e) * 144 + c] = acc[e] + bias;
    }
}

// ---------------------------------------------------------------------------
extern "C" void kernel_launch(void* const* d_in, const int* in_sizes, int n_in,
                              void* d_out, int out_size) {
    const float* atom_fea = (const float*)d_in[0];
    const float* edge_fea = (const float*)d_in[1];
    const int*   sai      = (const int*)  d_in[2];
    const int*   sei      = (const int*)  d_in[3];
    const float* ang      = (const float*)d_in[4];
    const int*   sidx     = (const int*)  d_in[5];
    const float* dist     = (const float*)d_in[6];
    const float* Wf       = (const float*)d_in[7];
    const float* bf       = (const float*)d_in[8];
    const float* Ws       = (const float*)d_in[9];
    const float* bs       = (const float*)d_in[10];
    const float* W1       = (const float*)d_in[11];
    const float* b1       = (const float*)d_in[12];
    const float* W2       = (const float*)d_in[13];
    const float* b2       = (const float*)d_in[14];
    float* out = (float*)d_out;

    static bool attr_done = false;
    if (!attr_done) {
        cudaFuncSetAttribute(kB,  cudaFuncAttributeMaxDynamicSharedMemorySize, 112*128*4 + 32*112*4);
        cudaFuncSetAttribute(kD1, cudaFuncAttributeMaxDynamicSharedMemorySize, 240*128*4 + 32*240*4);
        cudaFuncSetAttribute(kD2, cudaFuncAttributeMaxDynamicSharedMemorySize, 128*144*4 + 32*128*4);
        attr_done = true;
    }

    // zero scatter buffer
    {
        size_t n4 = (size_t)2 * NEg * 64 / 4;
        int blocks = (int)((n4 + 255) / 256);
        kZero<<<blocks, 256>>>();
    }
    // per-atom projections
    kA<<<(NA + 31) / 32, 256>>>(atom_fea, Wf, Ws);
    // per-edge projections
    kB<<<444, 256, 112*128*4 + 32*112*4>>>(edge_fea, Wf, Ws);
    // per-sub gather/gate/scatter
    kC<<<2048, 256>>>(sai, sei, ang, sidx, dist, Wf, bf, Ws, bs);
    // edge MLP
    kD1<<<148, 256, 240*128*4 + 32*240*4>>>(edge_fea, W1, b1);
    kD2<<<296, 288, 128*144*4 + 32*128*4>>>(W2, b2, out);
}